// round 14
// baseline (speedup 1.0000x reference)
#include <cuda_runtime.h>
#include <cuda_bf16.h>
#include <math.h>
#include <stdint.h>

#define T_TOK 4096
#define H_DIM 2048
#define I_DIM 6144

#define RMAGIC 12582912.f   // 1.5*2^23: fma(v,inv,RMAGIC)-RMAGIC = RNE(v*inv) for |q|<2^22

// ================= device scratch (static — no runtime alloc) =================
__device__ __align__(128) __nv_bfloat16 g_xh[(size_t)T_TOK * H_DIM];
__device__ __align__(128) __nv_bfloat16 g_xl[(size_t)T_TOK * H_DIM];
__device__ __align__(128) __nv_bfloat16 g_wu[(size_t)I_DIM * H_DIM];
__device__ __align__(128) __nv_bfloat16 g_wg[(size_t)I_DIM * H_DIM];
__device__ __align__(128) __nv_bfloat16 g_wd[(size_t)H_DIM * I_DIM];
__device__ __align__(128) float g_wsu[(size_t)(H_DIM / 32) * I_DIM];
__device__ __align__(128) float g_wsg[(size_t)(H_DIM / 32) * I_DIM];
__device__ __align__(128) float g_wsd[(size_t)(I_DIM / 32) * H_DIM];
__device__ __align__(128) __nv_bfloat16 g_mh[(size_t)T_TOK * I_DIM];
__device__ __align__(128) __nv_bfloat16 g_ml[(size_t)T_TOK * I_DIM];
__device__ __align__(128) float g_up[(size_t)T_TOK * I_DIM];
__device__ __align__(128) float g_gate[(size_t)T_TOK * I_DIM];
__device__ unsigned g_absmax[8]; // 0=x 1=|up| 2=|gate| 4=|mid| 5=max+(up)

#define SILU_TROUGH 0.27846455f

// ================= PTX helpers =================
__device__ __forceinline__ uint32_t smem_u32(const void* p) {
    uint32_t a;
    asm("{ .reg .u64 t; cvta.to.shared.u64 t, %1; cvt.u32.u64 %0, t; }" : "=r"(a) : "l"(p));
    return a;
}
__device__ __forceinline__ void cp16(uint32_t dst, const void* src) {
    asm volatile("cp.async.cg.shared.global [%0], [%1], 16;" :: "r"(dst), "l"(src));
}
#define CP_COMMIT() asm volatile("cp.async.commit_group;" ::: "memory")

#define LDSM4(r, addr) \
    asm volatile("ldmatrix.sync.aligned.m8n8.x4.shared.b16 {%0,%1,%2,%3}, [%4];" \
        : "=r"((r)[0]), "=r"((r)[1]), "=r"((r)[2]), "=r"((r)[3]) : "r"(addr))

#define MMA_BF16_ZC(d, a, b0, b1) \
    asm volatile("mma.sync.aligned.m16n8k16.row.col.f32.bf16.bf16.f32 " \
        "{%0,%1,%2,%3},{%4,%5,%6,%7},{%8,%9},{%10,%10,%10,%10};" \
        : "=f"((d)[0]), "=f"((d)[1]), "=f"((d)[2]), "=f"((d)[3]) \
        : "r"((a)[0]), "r"((a)[1]), "r"((a)[2]), "r"((a)[3]), \
          "r"(b0), "r"(b1), "f"(0.f))

#define MMA_BF16_ACC(d, a, b0, b1) \
    asm volatile("mma.sync.aligned.m16n8k16.row.col.f32.bf16.bf16.f32 " \
        "{%0,%1,%2,%3},{%4,%5,%6,%7},{%8,%9},{%0,%1,%2,%3};" \
        : "+f"((d)[0]), "+f"((d)[1]), "+f"((d)[2]), "+f"((d)[3]) \
        : "r"((a)[0]), "r"((a)[1]), "r"((a)[2]), "r"((a)[3]), "r"(b0), "r"(b1))

__device__ __forceinline__ float get_scale(int slot, float qmax) {
    return fmaxf(__uint_as_float(g_absmax[slot]) / qmax, 1e-12f);
}
__device__ __forceinline__ void warp_atomic_absmax(int slot, float v) {
    #pragma unroll
    for (int o = 16; o; o >>= 1) v = fmaxf(v, __shfl_xor_sync(0xffffffffu, v, o));
    if ((threadIdx.x & 31) == 0) atomicMax(&g_absmax[slot], __float_as_uint(v));
}
__device__ __forceinline__ uint32_t cvt_bf2(float lo, float hi) {
    uint32_t r;
    asm("cvt.rn.bf16x2.f32 %0, %1, %2;" : "=r"(r) : "f"(hi), "f"(lo));
    return r;
}
__device__ __forceinline__ float tanh_fast(float x) {
    float t;
    asm("tanh.approx.f32 %0, %1;" : "=f"(t) : "f"(x));
    return t;
}
__device__ __forceinline__ float silu_fast(float x) {
    float t = tanh_fast(0.5f * x);
    return x * fmaf(0.5f, t, 0.5f);
}
// round-to-nearest-even of v*inv via magic add (FMA pipe; exact for |result| < 2^22)
__device__ __forceinline__ float rne_scaled(float v, float inv) {
    return fmaf(v, inv, RMAGIC) - RMAGIC;
}

// ================= elementwise kernels =================
__global__ void k_zero() { if (threadIdx.x < 8) g_absmax[threadIdx.x] = 0u; }

__global__ void k_absmax4(const float4* __restrict__ x, size_t n4, int slot) {
    size_t i = (size_t)blockIdx.x * blockDim.x + threadIdx.x;
    size_t st = (size_t)gridDim.x * blockDim.x;
    float m = 0.f;
    for (; i < n4; i += st) {
        float4 v = x[i];
        m = fmaxf(m, fmaxf(fmaxf(fabsf(v.x), fabsf(v.y)), fmaxf(fabsf(v.z), fabsf(v.w))));
    }
    warp_atomic_absmax(slot, m);
}

// quantize -> int16 code -> exact bf16 planes (all rounding on the FMA pipe)
__global__ void k_split_bf16(const float4* __restrict__ in, uint4* __restrict__ oh,
                             uint4* __restrict__ ol, size_t n8, int slot) {
    float s = get_scale(slot, 32767.f);
    float inv = 1.f / s;
    size_t i = (size_t)blockIdx.x * blockDim.x + threadIdx.x;
    size_t st = (size_t)gridDim.x * blockDim.x;
    for (; i < n8; i += st) {
        float4 v0 = in[2 * i], v1 = in[2 * i + 1];
        float f[8] = {v0.x, v0.y, v0.z, v0.w, v1.x, v1.y, v1.z, v1.w};
        float fh[8], fl[8];
        #pragma unroll
        for (int e = 0; e < 8; e++) {
            float q = rne_scaled(f[e], inv);                 // |q| <= 32767
            float qh = rne_scaled(q, 0.00390625f) * 256.f;   // 256*RNE(q/256), exact
            fh[e] = qh;
            fl[e] = q - qh;
        }
        oh[i] = make_uint4(cvt_bf2(fh[0], fh[1]), cvt_bf2(fh[2], fh[3]),
                           cvt_bf2(fh[4], fh[5]), cvt_bf2(fh[6], fh[7]));
        ol[i] = make_uint4(cvt_bf2(fl[0], fl[1]), cvt_bf2(fl[2], fl[3]),
                           cvt_bf2(fl[4], fl[5]), cvt_bf2(fl[6], fl[7]));
    }
}

// merged LPBQ weight dequant for all three weights
__global__ void k_dqw_all(const float* __restrict__ wu, const float* __restrict__ wg,
                          const float* __restrict__ wd,
                          uint4* __restrict__ ou, uint4* __restrict__ og,
                          uint4* __restrict__ od,
                          float* __restrict__ su, float* __restrict__ sg,
                          float* __restrict__ sd) {
    const size_t NB = (size_t)I_DIM * H_DIM / 32;
    size_t i = (size_t)blockIdx.x * blockDim.x + threadIdx.x;
    size_t st = (size_t)gridDim.x * blockDim.x;
    for (; i < 3 * NB; i += st) {
        int seg = (int)(i / NB);
        size_t r = i - (size_t)seg * NB;
        const float* w; uint4* oq; float* ws; int N, K;
        if (seg == 0)      { w = wu; oq = ou; ws = su; N = I_DIM; K = H_DIM; }
        else if (seg == 1) { w = wg; oq = og; ws = sg; N = I_DIM; K = H_DIM; }
        else               { w = wd; oq = od; ws = sd; N = H_DIM; K = I_DIM; }
        int kb = K / 32;
        int n = (int)(r / kb);
        int b = (int)(r % kb);
        const float4* p = (const float4*)(w + (size_t)n * K + b * 32);
        float4 v[8];
        float m = 0.f;
        #pragma unroll
        for (int j = 0; j < 8; j++) {
            v[j] = p[j];
            m = fmaxf(m, fmaxf(fmaxf(fabsf(v[j].x), fabsf(v[j].y)),
                               fmaxf(fabsf(v[j].z), fabsf(v[j].w))));
        }
        float s = fmaxf(m / 7.0f, 1e-12f);
        float inv = 1.f / s;
        uint32_t cw[16];
        #pragma unroll
        for (int j = 0; j < 8; j++) {
            float q0 = rne_scaled(v[j].x, inv), q1 = rne_scaled(v[j].y, inv);
            float q2 = rne_scaled(v[j].z, inv), q3 = rne_scaled(v[j].w, inv);
            cw[2 * j]     = cvt_bf2(q0, q1);
            cw[2 * j + 1] = cvt_bf2(q2, q3);
        }
        uint4* dst = oq + ((size_t)n * K + b * 32) / 8;
        #pragma unroll
        for (int j = 0; j < 4; j++)
            dst[j] = make_uint4(cw[4 * j], cw[4 * j + 1], cw[4 * j + 2], cw[4 * j + 3]);
        ws[(size_t)b * N + n] = s;
    }
}

// fused act+mul, all rounding on FMA pipe; mid = code_a*code_g*(s2*s3)
__global__ void k_actmul(size_t n4) {
    float s1 = get_scale(1, 32767.f);
    float inv1 = 1.f / s1;
    float s2 = get_scale(2, 32767.f);
    float inv2 = 1.f / s2;
    float maxpos = __uint_as_float(g_absmax[5]);
    float uqm = rne_scaled(maxpos, inv1) * s1;
    float amax_act = fmaxf(silu_fast(uqm), SILU_TROUGH);
    float s3 = fmaxf(amax_act / 32767.f, 1e-12f);
    float inv3 = 1.f / s3;
    float s23 = s2 * s3;

    const float4* up = (const float4*)g_up;
    float4* gt = (float4*)g_gate;
    size_t i = (size_t)blockIdx.x * blockDim.x + threadIdx.x;
    size_t st = (size_t)gridDim.x * blockDim.x;
    float m = 0.f;
    for (; i < n4; i += st) {
        float4 u = up[i];
        float4 g = gt[i];
        float fu[4] = {u.x, u.y, u.z, u.w};
        float fg[4] = {g.x, g.y, g.z, g.w};
        #pragma unroll
        for (int e = 0; e < 4; e++) {
            float uq = rne_scaled(fu[e], inv1) * s1;
            float a = silu_fast(uq);
            float ca = rne_scaled(a, inv3);      // act code
            float cg = rne_scaled(fg[e], inv2);  // gate code
            float mv = ca * cg * s23;
            fg[e] = mv;
            m = fmaxf(m, fabsf(mv));
        }
        gt[i] = make_float4(fg[0], fg[1], fg[2], fg[3]);
    }
    warp_atomic_absmax(4, m);
}

// ================= 2-term scaled-code bf16 GEMM (exact) =================
#define BM 128
#define BN 256
#define BK 64
#define STAGES 3
#define A_PL (BM * BK * 2)
#define B_PL (BN * BK * 2)
#define STAGE_BYTES (2 * A_PL + B_PL)       // 65536
#define GEMM_SMEM (STAGES * STAGE_BYTES)    // 196608

__device__ __forceinline__ void load_stage(
    int c, int m0, int n0, int K, int tid, uint32_t sbase,
    const __nv_bfloat16* __restrict__ Ah, const __nv_bfloat16* __restrict__ Al,
    const __nv_bfloat16* __restrict__ Bc) {
    int kk = c * BK;
    uint32_t st = sbase + (uint32_t)(c % STAGES) * STAGE_BYTES;
    int arow = tid >> 1;
    int ac0 = (tid & 1) * 4;
    size_t aoff = (size_t)(m0 + arow) * K + kk + ac0 * 8;
    uint32_t abase = st + (uint32_t)arow * 128;
    #pragma unroll
    for (int j = 0; j < 4; j++) {
        uint32_t so = (uint32_t)(((ac0 + j) ^ (arow & 7)) << 4);
        cp16(abase + so, Ah + aoff + j * 8);
        cp16(abase + A_PL + so, Al + aoff + j * 8);
    }
    const __nv_bfloat16* bg = Bc + (size_t)(n0 + tid) * K + kk;
    uint32_t bbase = st + 2 * A_PL + (uint32_t)tid * 128;
    #pragma unroll
    for (int j = 0; j < 8; j++)
        cp16(bbase + (uint32_t)((j ^ (tid & 7)) << 4), bg + j * 8);
    CP_COMMIT();
}

__global__ void __launch_bounds__(256, 1)
k_gemm_sc(const __nv_bfloat16* __restrict__ Ah, const __nv_bfloat16* __restrict__ Al,
          const __nv_bfloat16* __restrict__ B0, const float* __restrict__ Ws0,
          float* __restrict__ C0, int so0,
          const __nv_bfloat16* __restrict__ B1, const float* __restrict__ Ws1,
          float* __restrict__ C1, int so1,
          int halfX, int N, int K, int slot_in) {
    extern __shared__ char smem[];
    const uint32_t sbase = smem_u32(smem);
    const int tid = threadIdx.x, wid = tid >> 5, lane = tid & 31;
    const int wm = wid >> 2, wn = wid & 3;
    const bool second = ((int)blockIdx.x >= halfX);
    const int nblk = second ? ((int)blockIdx.x - halfX) : (int)blockIdx.x;
    const __nv_bfloat16* Bc = second ? B1 : B0;
    const float* WsT = second ? Ws1 : Ws0;
    float* C = second ? C1 : C0;
    const int slot_out = second ? so1 : so0;
    const int m0 = blockIdx.y * BM, n0 = nblk * BN;
    const int chunks = K / BK;

    float facc[4][8][4];
    #pragma unroll
    for (int i = 0; i < 4; i++)
        #pragma unroll
        for (int j = 0; j < 8; j++)
            #pragma unroll
            for (int e = 0; e < 4; e++) facc[i][j][e] = 0.f;

    const int a_ro = (lane & 7) + ((lane & 8) ? 8 : 0);
    const int a_chk = (lane >> 4) & 1;
    const int b_ro = (lane & 7) + ((lane & 16) ? 8 : 0);
    const int b_chk = (lane >> 3) & 1;

    load_stage(0, m0, n0, K, tid, sbase, Ah, Al, Bc);
    load_stage(1, m0, n0, K, tid, sbase, Ah, Al, Bc);

    for (int c = 0; c < chunks; ++c) {
        if (c + 1 < chunks) asm volatile("cp.async.wait_group 1;" ::: "memory");
        else                asm volatile("cp.async.wait_group 0;" ::: "memory");
        __syncthreads();
        if (c + STAGES - 1 < chunks)
            load_stage(c + STAGES - 1, m0, n0, K, tid, sbase, Ah, Al, Bc);

        uint32_t st = sbase + (uint32_t)(c % STAGES) * STAGE_BYTES;
        uint32_t sAh = st, sAl = st + A_PL, sB = st + 2 * A_PL;

        #pragma unroll
        for (int kb = 0; kb < 2; kb++) {
            const float* wsr = WsT + (size_t)(c * 2 + kb) * N + n0 + wn * 64 + (lane & 3) * 2;
            float2 sc[8];
            #pragma unroll
            for (int j = 0; j < 8; j++) sc[j] = __ldg((const float2*)(wsr + j * 8));

            #pragma unroll
            for (int ks2 = 0; ks2 < 2; ks2++) {
                int ks = kb * 2 + ks2;
                uint32_t ah[4][4], al[4][4], bb[4][4];
                #pragma unroll
                for (int i = 0; i < 4; i++) {
                    int row = wm * 64 + i * 16 + a_ro;
                    uint32_t so = (uint32_t)(((2 * ks + a_chk) ^ (row & 7)) << 4);
                    LDSM4(ah[i], sAh + (uint32_t)row * 128 + so);
                    LDSM4(al[i], sAl + (uint32_t)row * 128 + so);
                }
                #pragma unroll
                for (int j = 0; j < 4; j++) {
                    int row = wn * 64 + j * 16 + b_ro;
                    uint32_t so = (uint32_t)(((2 * ks + b_chk) ^ (row & 7)) << 4);
                    LDSM4(bb[j], sB + (uint32_t)row * 128 + so);
                }
                #pragma unroll
                for (int i = 0; i < 4; i++)
                    #pragma unroll
                    for (int j2 = 0; j2 < 8; j2++) {
                        uint32_t b0 = bb[j2 >> 1][(j2 & 1) * 2];
                        uint32_t b1 = bb[j2 >> 1][(j2 & 1) * 2 + 1];
                        float Pb[4];
                        MMA_BF16_ZC(Pb, ah[i], b0, b1);
                        MMA_BF16_ACC(Pb, al[i], b0, b1);
                        facc[i][j2][0] = fmaf(Pb[0], sc[j2].x, facc[i][j2][0]);
                        facc[i][j2][1] = fmaf(Pb[1], sc[j2].y, facc[i][j2][1]);
                        facc[i][j2][2] = fmaf(Pb[2], sc[j2].x, facc[i][j2][2]);
                        facc[i][j2][3] = fmaf(Pb[3], sc[j2].y, facc[i][j2][3]);
                    }
            }
        }
    }

    float s = get_scale(slot_in, 32767.f);
    const int g = lane >> 2, q = lane & 3;
    float mx = 0.f, mpos = 0.f;
    #pragma unroll
    for (int i = 0; i < 4; i++) {
        #pragma unroll
        for (int j2 = 0; j2 < 8; j2++) {
            int row = m0 + wm * 64 + i * 16 + g;
            int col = n0 + wn * 64 + j2 * 8 + q * 2;
            float v0 = facc[i][j2][0] * s, v1 = facc[i][j2][1] * s;
            float v2 = facc[i][j2][2] * s, v3 = facc[i][j2][3] * s;
            *(float2*)&C[(size_t)row * N + col] = make_float2(v0, v1);
            *(float2*)&C[(size_t)(row + 8) * N + col] = make_float2(v2, v3);
            mx = fmaxf(mx, fmaxf(fmaxf(fabsf(v0), fabsf(v1)), fmaxf(fabsf(v2), fabsf(v3))));
            mpos = fmaxf(mpos, fmaxf(fmaxf(v0, v1), fmaxf(v2, v3)));
        }
    }
    if (slot_out >= 0) warp_atomic_absmax(slot_out, mx);
    if (slot_out == 1) warp_atomic_absmax(5, fmaxf(mpos, 0.f));
}

// ================= host =================
extern "C" void kernel_launch(void* const* d_in, const int* in_sizes, int n_in,
                              void* d_out, int out_size) {
    const float* x      = (const float*)d_in[0];
    const float* w_gate = (const float*)d_in[1];
    const float* w_up   = (const float*)d_in[2];
    const float* w_down = (const float*)d_in[3];
    float* out = (float*)d_out;

    void *p_xh, *p_xl, *p_wu, *p_wg, *p_wd, *p_wsu, *p_wsg, *p_wsd;
    void *p_mh, *p_ml, *p_up, *p_gate;
    cudaGetSymbolAddress(&p_xh, g_xh);   cudaGetSymbolAddress(&p_xl, g_xl);
    cudaGetSymbolAddress(&p_wu, g_wu);   cudaGetSymbolAddress(&p_wg, g_wg);
    cudaGetSymbolAddress(&p_wd, g_wd);
    cudaGetSymbolAddress(&p_wsu, g_wsu); cudaGetSymbolAddress(&p_wsg, g_wsg);
    cudaGetSymbolAddress(&p_wsd, g_wsd);
    cudaGetSymbolAddress(&p_mh, g_mh);   cudaGetSymbolAddress(&p_ml, g_ml);
    cudaGetSymbolAddress(&p_up, g_up);   cudaGetSymbolAddress(&p_gate, g_gate);

    static bool once = false;
    if (!once) {
        cudaFuncSetAttribute(k_gemm_sc, cudaFuncAttributeMaxDynamicSharedMemorySize, GEMM_SMEM);
        once = true;
    }

    const int GS = 1184;
    const size_t nx4 = (size_t)T_TOK * H_DIM / 4;
    const size_t nx8 = (size_t)T_TOK * H_DIM / 8;
    const size_t nti4 = (size_t)T_TOK * I_DIM / 4;
    const size_t nti8 = (size_t)T_TOK * I_DIM / 8;

    k_zero<<<1, 32>>>();
    k_absmax4<<<GS, 256>>>((const float4*)x, nx4, 0);
    k_split_bf16<<<GS, 256>>>((const float4*)x, (uint4*)p_xh, (uint4*)p_xl, nx8, 0);
    k_dqw_all<<<GS, 256>>>(w_up, w_gate, w_down,
                           (uint4*)p_wu, (uint4*)p_wg, (uint4*)p_wd,
                           (float*)p_wsu, (float*)p_wsg, (float*)p_wsd);

    dim3 g1(2 * (I_DIM / BN), T_TOK / BM);   // 48 x 32
    k_gemm_sc<<<g1, 256, GEMM_SMEM>>>(
        (const __nv_bfloat16*)p_xh, (const __nv_bfloat16*)p_xl,
        (const __nv_bfloat16*)p_wu, (const float*)p_wsu, (float*)p_up, 1,
        (const __nv_bfloat16*)p_wg, (const float*)p_wsg, (float*)p_gate, 2,
        I_DIM / BN, I_DIM, H_DIM, 0);

    k_actmul<<<GS, 256>>>(nti4);
    k_split_bf16<<<GS, 256>>>((const float4*)p_gate, (uint4*)p_mh, (uint4*)p_ml, nti8, 4);

    dim3 g3(H_DIM / BN, T_TOK / BM);   // 8 x 32
    k_gemm_sc<<<g3, 256, GEMM_SMEM>>>(
        (const __nv_bfloat16*)p_mh, (const __nv_bfloat16*)p_ml,
        (const __nv_bfloat16*)p_wd, (const float*)p_wsd, out, -1,
        (const __nv_bfloat16*)p_wd, (const float*)p_wsd, out, -1,
        H_DIM / BN, H_DIM, I_DIM, 4);
}

// round 15
// speedup vs baseline: 1.0138x; 1.0138x over previous
#include <cuda_runtime.h>
#include <cuda_bf16.h>
#include <math.h>
#include <stdint.h>

#define T_TOK 4096
#define H_DIM 2048
#define I_DIM 6144

#define RMAGIC 12582912.f   // 1.5*2^23: fma(v,inv,RMAGIC)-RMAGIC = RNE(v*inv) for |q|<2^22

// ================= device scratch (static — no runtime alloc) =================
__device__ __align__(128) __nv_bfloat16 g_xh[(size_t)T_TOK * H_DIM];
__device__ __align__(128) __nv_bfloat16 g_xl[(size_t)T_TOK * H_DIM];
__device__ __align__(128) __nv_bfloat16 g_wu[(size_t)I_DIM * H_DIM];
__device__ __align__(128) __nv_bfloat16 g_wg[(size_t)I_DIM * H_DIM];
__device__ __align__(128) __nv_bfloat16 g_wd[(size_t)H_DIM * I_DIM];
__device__ __align__(128) float g_wsu[(size_t)(H_DIM / 32) * I_DIM];
__device__ __align__(128) float g_wsg[(size_t)(H_DIM / 32) * I_DIM];
__device__ __align__(128) float g_wsd[(size_t)(I_DIM / 32) * H_DIM];
__device__ __align__(128) __nv_bfloat16 g_mh[(size_t)T_TOK * I_DIM];
__device__ __align__(128) __nv_bfloat16 g_ml[(size_t)T_TOK * I_DIM];
__device__ __align__(128) float g_up[(size_t)T_TOK * I_DIM];
__device__ __align__(128) float g_gate[(size_t)T_TOK * I_DIM];
__device__ unsigned g_absmax[8]; // 0=x 1=|up| 2=|gate| 4=s4_b*32767 5=max+(up)

#define SILU_TROUGH 0.27846455f

// ================= PTX helpers =================
__device__ __forceinline__ uint32_t smem_u32(const void* p) {
    uint32_t a;
    asm("{ .reg .u64 t; cvta.to.shared.u64 t, %1; cvt.u32.u64 %0, t; }" : "=r"(a) : "l"(p));
    return a;
}
__device__ __forceinline__ void cp16(uint32_t dst, const void* src) {
    asm volatile("cp.async.cg.shared.global [%0], [%1], 16;" :: "r"(dst), "l"(src));
}
#define CP_COMMIT() asm volatile("cp.async.commit_group;" ::: "memory")

#define LDSM4(r, addr) \
    asm volatile("ldmatrix.sync.aligned.m8n8.x4.shared.b16 {%0,%1,%2,%3}, [%4];" \
        : "=r"((r)[0]), "=r"((r)[1]), "=r"((r)[2]), "=r"((r)[3]) : "r"(addr))

#define MMA_BF16_ZC(d, a, b0, b1) \
    asm volatile("mma.sync.aligned.m16n8k16.row.col.f32.bf16.bf16.f32 " \
        "{%0,%1,%2,%3},{%4,%5,%6,%7},{%8,%9},{%10,%10,%10,%10};" \
        : "=f"((d)[0]), "=f"((d)[1]), "=f"((d)[2]), "=f"((d)[3]) \
        : "r"((a)[0]), "r"((a)[1]), "r"((a)[2]), "r"((a)[3]), \
          "r"(b0), "r"(b1), "f"(0.f))

#define MMA_BF16_ACC(d, a, b0, b1) \
    asm volatile("mma.sync.aligned.m16n8k16.row.col.f32.bf16.bf16.f32 " \
        "{%0,%1,%2,%3},{%4,%5,%6,%7},{%8,%9},{%0,%1,%2,%3};" \
        : "+f"((d)[0]), "+f"((d)[1]), "+f"((d)[2]), "+f"((d)[3]) \
        : "r"((a)[0]), "r"((a)[1]), "r"((a)[2]), "r"((a)[3]), "r"(b0), "r"(b1))

__device__ __forceinline__ float get_scale(int slot, float qmax) {
    return fmaxf(__uint_as_float(g_absmax[slot]) / qmax, 1e-12f);
}
__device__ __forceinline__ void warp_atomic_absmax(int slot, float v) {
    #pragma unroll
    for (int o = 16; o; o >>= 1) v = fmaxf(v, __shfl_xor_sync(0xffffffffu, v, o));
    if ((threadIdx.x & 31) == 0) atomicMax(&g_absmax[slot], __float_as_uint(v));
}
__device__ __forceinline__ uint32_t cvt_bf2(float lo, float hi) {
    uint32_t r;
    asm("cvt.rn.bf16x2.f32 %0, %1, %2;" : "=r"(r) : "f"(hi), "f"(lo));
    return r;
}
__device__ __forceinline__ float tanh_fast(float x) {
    float t;
    asm("tanh.approx.f32 %0, %1;" : "=f"(t) : "f"(x));
    return t;
}
__device__ __forceinline__ float silu_fast(float x) {
    float t = tanh_fast(0.5f * x);
    return x * fmaf(0.5f, t, 0.5f);
}
__device__ __forceinline__ float rne_scaled(float v, float inv) {
    return fmaf(v, inv, RMAGIC) - RMAGIC;
}

// ================= elementwise kernels =================
__global__ void k_zero() { if (threadIdx.x < 8) g_absmax[threadIdx.x] = 0u; }

__global__ void k_absmax4(const float4* __restrict__ x, size_t n4, int slot) {
    size_t i = (size_t)blockIdx.x * blockDim.x + threadIdx.x;
    size_t st = (size_t)gridDim.x * blockDim.x;
    float m = 0.f;
    for (; i < n4; i += st) {
        float4 v = x[i];
        m = fmaxf(m, fmaxf(fmaxf(fabsf(v.x), fabsf(v.y)), fmaxf(fabsf(v.z), fabsf(v.w))));
    }
    warp_atomic_absmax(slot, m);
}

// quantize x -> int16 code -> exact bf16 planes
__global__ void k_split_bf16(const float4* __restrict__ in, uint4* __restrict__ oh,
                             uint4* __restrict__ ol, size_t n8, int slot) {
    float s = get_scale(slot, 32767.f);
    float inv = 1.f / s;
    size_t i = (size_t)blockIdx.x * blockDim.x + threadIdx.x;
    size_t st = (size_t)gridDim.x * blockDim.x;
    for (; i < n8; i += st) {
        float4 v0 = in[2 * i], v1 = in[2 * i + 1];
        float f[8] = {v0.x, v0.y, v0.z, v0.w, v1.x, v1.y, v1.z, v1.w};
        float fh[8], fl[8];
        #pragma unroll
        for (int e = 0; e < 8; e++) {
            float q = rne_scaled(f[e], inv);
            float qh = rne_scaled(q, 0.00390625f) * 256.f;
            fh[e] = qh;
            fl[e] = q - qh;
        }
        oh[i] = make_uint4(cvt_bf2(fh[0], fh[1]), cvt_bf2(fh[2], fh[3]),
                           cvt_bf2(fh[4], fh[5]), cvt_bf2(fh[6], fh[7]));
        ol[i] = make_uint4(cvt_bf2(fl[0], fl[1]), cvt_bf2(fl[2], fl[3]),
                           cvt_bf2(fl[4], fl[5]), cvt_bf2(fl[6], fl[7]));
    }
}

// merged LPBQ weight dequant for all three weights
__global__ void k_dqw_all(const float* __restrict__ wu, const float* __restrict__ wg,
                          const float* __restrict__ wd,
                          uint4* __restrict__ ou, uint4* __restrict__ og,
                          uint4* __restrict__ od,
                          float* __restrict__ su, float* __restrict__ sg,
                          float* __restrict__ sd) {
    const size_t NB = (size_t)I_DIM * H_DIM / 32;
    size_t i = (size_t)blockIdx.x * blockDim.x + threadIdx.x;
    size_t st = (size_t)gridDim.x * blockDim.x;
    for (; i < 3 * NB; i += st) {
        int seg = (int)(i / NB);
        size_t r = i - (size_t)seg * NB;
        const float* w; uint4* oq; float* ws; int N, K;
        if (seg == 0)      { w = wu; oq = ou; ws = su; N = I_DIM; K = H_DIM; }
        else if (seg == 1) { w = wg; oq = og; ws = sg; N = I_DIM; K = H_DIM; }
        else               { w = wd; oq = od; ws = sd; N = H_DIM; K = I_DIM; }
        int kb = K / 32;
        int n = (int)(r / kb);
        int b = (int)(r % kb);
        const float4* p = (const float4*)(w + (size_t)n * K + b * 32);
        float4 v[8];
        float m = 0.f;
        #pragma unroll
        for (int j = 0; j < 8; j++) {
            v[j] = p[j];
            m = fmaxf(m, fmaxf(fmaxf(fabsf(v[j].x), fabsf(v[j].y)),
                               fmaxf(fabsf(v[j].z), fabsf(v[j].w))));
        }
        float s = fmaxf(m / 7.0f, 1e-12f);
        float inv = 1.f / s;
        uint32_t cw[16];
        #pragma unroll
        for (int j = 0; j < 8; j++) {
            float q0 = rne_scaled(v[j].x, inv), q1 = rne_scaled(v[j].y, inv);
            float q2 = rne_scaled(v[j].z, inv), q3 = rne_scaled(v[j].w, inv);
            cw[2 * j]     = cvt_bf2(q0, q1);
            cw[2 * j + 1] = cvt_bf2(q2, q3);
        }
        uint4* dst = oq + ((size_t)n * K + b * 32) / 8;
        #pragma unroll
        for (int j = 0; j < 4; j++)
            dst[j] = make_uint4(cw[4 * j], cw[4 * j + 1], cw[4 * j + 2], cw[4 * j + 3]);
        ws[(size_t)b * N + n] = s;
    }
}

// fused act+mul+split: mid code = RNE(ca*cg/32767) with analytic s4_b = s2*s3*32767
// (|mid| <= 32767*s3 * 32767*s2 => codes within [-32767,32767]); emits bf16 planes directly.
__global__ void k_actmul_split(uint4* __restrict__ oh, uint4* __restrict__ ol, size_t n8) {
    float s1 = get_scale(1, 32767.f);
    float inv1 = 1.f / s1;
    float s2 = get_scale(2, 32767.f);
    float inv2 = 1.f / s2;
    float maxpos = __uint_as_float(g_absmax[5]);
    float uqm = rne_scaled(maxpos, inv1) * s1;
    float amax_act = fmaxf(silu_fast(uqm), SILU_TROUGH);
    float s3 = fmaxf(amax_act / 32767.f, 1e-12f);
    float inv3 = 1.f / s3;
    // publish s4_b to slot 4: get_scale(4) = s2*s3*32767  (32767^2 = 1073676289)
    if (blockIdx.x == 0 && threadIdx.x == 0)
        g_absmax[4] = __float_as_uint(s2 * s3 * 1073676289.f);

    const float4* up = (const float4*)g_up;
    const float4* gt = (const float4*)g_gate;
    const float inv327 = 1.f / 32767.f;
    size_t i = (size_t)blockIdx.x * blockDim.x + threadIdx.x;
    size_t st = (size_t)gridDim.x * blockDim.x;
    for (; i < n8; i += st) {
        float4 u0 = up[2 * i], u1 = up[2 * i + 1];
        float4 g0 = gt[2 * i], g1 = gt[2 * i + 1];
        float fu[8] = {u0.x, u0.y, u0.z, u0.w, u1.x, u1.y, u1.z, u1.w};
        float fg[8] = {g0.x, g0.y, g0.z, g0.w, g1.x, g1.y, g1.z, g1.w};
        float fh[8], fl[8];
        #pragma unroll
        for (int e = 0; e < 8; e++) {
            float uq = rne_scaled(fu[e], inv1) * s1;
            float a = silu_fast(uq);
            float ca = rne_scaled(a, inv3);        // act code
            float cg = rne_scaled(fg[e], inv2);    // gate code
            float q = rne_scaled(ca * cg, inv327); // mid code, |q| <= 32767
            float qh = rne_scaled(q, 0.00390625f) * 256.f;
            fh[e] = qh;
            fl[e] = q - qh;
        }
        oh[i] = make_uint4(cvt_bf2(fh[0], fh[1]), cvt_bf2(fh[2], fh[3]),
                           cvt_bf2(fh[4], fh[5]), cvt_bf2(fh[6], fh[7]));
        ol[i] = make_uint4(cvt_bf2(fl[0], fl[1]), cvt_bf2(fl[2], fl[3]),
                           cvt_bf2(fl[4], fl[5]), cvt_bf2(fl[6], fl[7]));
    }
}

// ================= 2-term scaled-code bf16 GEMM (exact) =================
#define BM 128
#define BN 256
#define BK 64
#define STAGES 3
#define A_PL (BM * BK * 2)
#define B_PL (BN * BK * 2)
#define STAGE_BYTES (2 * A_PL + B_PL)       // 65536
#define GEMM_SMEM (STAGES * STAGE_BYTES)    // 196608

__device__ __forceinline__ void load_stage(
    int c, int m0, int n0, int K, int tid, uint32_t sbase,
    const __nv_bfloat16* __restrict__ Ah, const __nv_bfloat16* __restrict__ Al,
    const __nv_bfloat16* __restrict__ Bc) {
    int kk = c * BK;
    uint32_t st = sbase + (uint32_t)(c % STAGES) * STAGE_BYTES;
    int arow = tid >> 1;
    int ac0 = (tid & 1) * 4;
    size_t aoff = (size_t)(m0 + arow) * K + kk + ac0 * 8;
    uint32_t abase = st + (uint32_t)arow * 128;
    #pragma unroll
    for (int j = 0; j < 4; j++) {
        uint32_t so = (uint32_t)(((ac0 + j) ^ (arow & 7)) << 4);
        cp16(abase + so, Ah + aoff + j * 8);
        cp16(abase + A_PL + so, Al + aoff + j * 8);
    }
    const __nv_bfloat16* bg = Bc + (size_t)(n0 + tid) * K + kk;
    uint32_t bbase = st + 2 * A_PL + (uint32_t)tid * 128;
    #pragma unroll
    for (int j = 0; j < 8; j++)
        cp16(bbase + (uint32_t)((j ^ (tid & 7)) << 4), bg + j * 8);
    CP_COMMIT();
}

__global__ void __launch_bounds__(256, 1)
k_gemm_sc(const __nv_bfloat16* __restrict__ Ah, const __nv_bfloat16* __restrict__ Al,
          const __nv_bfloat16* __restrict__ B0, const float* __restrict__ Ws0,
          float* __restrict__ C0, int so0,
          const __nv_bfloat16* __restrict__ B1, const float* __restrict__ Ws1,
          float* __restrict__ C1, int so1,
          int halfX, int N, int K, int slot_in) {
    extern __shared__ char smem[];
    const uint32_t sbase = smem_u32(smem);
    const int tid = threadIdx.x, wid = tid >> 5, lane = tid & 31;
    const int wm = wid >> 2, wn = wid & 3;
    const bool second = ((int)blockIdx.x >= halfX);
    const int nblk = second ? ((int)blockIdx.x - halfX) : (int)blockIdx.x;
    const __nv_bfloat16* Bc = second ? B1 : B0;
    const float* WsT = second ? Ws1 : Ws0;
    float* C = second ? C1 : C0;
    const int slot_out = second ? so1 : so0;
    const int m0 = blockIdx.y * BM, n0 = nblk * BN;
    const int chunks = K / BK;

    float facc[4][8][4];
    #pragma unroll
    for (int i = 0; i < 4; i++)
        #pragma unroll
        for (int j = 0; j < 8; j++)
            #pragma unroll
            for (int e = 0; e < 4; e++) facc[i][j][e] = 0.f;

    const int a_ro = (lane & 7) + ((lane & 8) ? 8 : 0);
    const int a_chk = (lane >> 4) & 1;
    const int b_ro = (lane & 7) + ((lane & 16) ? 8 : 0);
    const int b_chk = (lane >> 3) & 1;

    load_stage(0, m0, n0, K, tid, sbase, Ah, Al, Bc);
    load_stage(1, m0, n0, K, tid, sbase, Ah, Al, Bc);

    for (int c = 0; c < chunks; ++c) {
        if (c + 1 < chunks) asm volatile("cp.async.wait_group 1;" ::: "memory");
        else                asm volatile("cp.async.wait_group 0;" ::: "memory");
        __syncthreads();
        if (c + STAGES - 1 < chunks)
            load_stage(c + STAGES - 1, m0, n0, K, tid, sbase, Ah, Al, Bc);

        uint32_t st = sbase + (uint32_t)(c % STAGES) * STAGE_BYTES;
        uint32_t sAh = st, sAl = st + A_PL, sB = st + 2 * A_PL;

        #pragma unroll
        for (int kb = 0; kb < 2; kb++) {
            const float* wsr = WsT + (size_t)(c * 2 + kb) * N + n0 + wn * 64 + (lane & 3) * 2;
            float2 sc[8];
            #pragma unroll
            for (int j = 0; j < 8; j++) sc[j] = __ldg((const float2*)(wsr + j * 8));

            #pragma unroll
            for (int ks2 = 0; ks2 < 2; ks2++) {
                int ks = kb * 2 + ks2;
                uint32_t ah[4][4], al[4][4], bb[4][4];
                #pragma unroll
                for (int i = 0; i < 4; i++) {
                    int row = wm * 64 + i * 16 + a_ro;
                    uint32_t so = (uint32_t)(((2 * ks + a_chk) ^ (row & 7)) << 4);
                    LDSM4(ah[i], sAh + (uint32_t)row * 128 + so);
                    LDSM4(al[i], sAl + (uint32_t)row * 128 + so);
                }
                #pragma unroll
                for (int j = 0; j < 4; j++) {
                    int row = wn * 64 + j * 16 + b_ro;
                    uint32_t so = (uint32_t)(((2 * ks + b_chk) ^ (row & 7)) << 4);
                    LDSM4(bb[j], sB + (uint32_t)row * 128 + so);
                }
                #pragma unroll
                for (int i = 0; i < 4; i++)
                    #pragma unroll
                    for (int j2 = 0; j2 < 8; j2++) {
                        uint32_t b0 = bb[j2 >> 1][(j2 & 1) * 2];
                        uint32_t b1 = bb[j2 >> 1][(j2 & 1) * 2 + 1];
                        float Pb[4];
                        MMA_BF16_ZC(Pb, ah[i], b0, b1);
                        MMA_BF16_ACC(Pb, al[i], b0, b1);
                        facc[i][j2][0] = fmaf(Pb[0], sc[j2].x, facc[i][j2][0]);
                        facc[i][j2][1] = fmaf(Pb[1], sc[j2].y, facc[i][j2][1]);
                        facc[i][j2][2] = fmaf(Pb[2], sc[j2].x, facc[i][j2][2]);
                        facc[i][j2][3] = fmaf(Pb[3], sc[j2].y, facc[i][j2][3]);
                    }
            }
        }
    }

    float s = get_scale(slot_in, 32767.f);
    const int g = lane >> 2, q = lane & 3;
    float mx = 0.f, mpos = 0.f;
    #pragma unroll
    for (int i = 0; i < 4; i++) {
        #pragma unroll
        for (int j2 = 0; j2 < 8; j2++) {
            int row = m0 + wm * 64 + i * 16 + g;
            int col = n0 + wn * 64 + j2 * 8 + q * 2;
            float v0 = facc[i][j2][0] * s, v1 = facc[i][j2][1] * s;
            float v2 = facc[i][j2][2] * s, v3 = facc[i][j2][3] * s;
            *(float2*)&C[(size_t)row * N + col] = make_float2(v0, v1);
            *(float2*)&C[(size_t)(row + 8) * N + col] = make_float2(v2, v3);
            mx = fmaxf(mx, fmaxf(fmaxf(fabsf(v0), fabsf(v1)), fmaxf(fabsf(v2), fabsf(v3))));
            mpos = fmaxf(mpos, fmaxf(fmaxf(v0, v1), fmaxf(v2, v3)));
        }
    }
    if (slot_out >= 0) warp_atomic_absmax(slot_out, mx);
    if (slot_out == 1) warp_atomic_absmax(5, fmaxf(mpos, 0.f));
}

// ================= host =================
extern "C" void kernel_launch(void* const* d_in, const int* in_sizes, int n_in,
                              void* d_out, int out_size) {
    const float* x      = (const float*)d_in[0];
    const float* w_gate = (const float*)d_in[1];
    const float* w_up   = (const float*)d_in[2];
    const float* w_down = (const float*)d_in[3];
    float* out = (float*)d_out;

    void *p_xh, *p_xl, *p_wu, *p_wg, *p_wd, *p_wsu, *p_wsg, *p_wsd;
    void *p_mh, *p_ml, *p_up, *p_gate;
    cudaGetSymbolAddress(&p_xh, g_xh);   cudaGetSymbolAddress(&p_xl, g_xl);
    cudaGetSymbolAddress(&p_wu, g_wu);   cudaGetSymbolAddress(&p_wg, g_wg);
    cudaGetSymbolAddress(&p_wd, g_wd);
    cudaGetSymbolAddress(&p_wsu, g_wsu); cudaGetSymbolAddress(&p_wsg, g_wsg);
    cudaGetSymbolAddress(&p_wsd, g_wsd);
    cudaGetSymbolAddress(&p_mh, g_mh);   cudaGetSymbolAddress(&p_ml, g_ml);
    cudaGetSymbolAddress(&p_up, g_up);   cudaGetSymbolAddress(&p_gate, g_gate);

    static bool once = false;
    if (!once) {
        cudaFuncSetAttribute(k_gemm_sc, cudaFuncAttributeMaxDynamicSharedMemorySize, GEMM_SMEM);
        once = true;
    }

    const int GS = 1184;
    const size_t nx4 = (size_t)T_TOK * H_DIM / 4;
    const size_t nx8 = (size_t)T_TOK * H_DIM / 8;
    const size_t nti8 = (size_t)T_TOK * I_DIM / 8;

    k_zero<<<1, 32>>>();
    k_absmax4<<<GS, 256>>>((const float4*)x, nx4, 0);
    k_split_bf16<<<GS, 256>>>((const float4*)x, (uint4*)p_xh, (uint4*)p_xl, nx8, 0);
    k_dqw_all<<<GS, 256>>>(w_up, w_gate, w_down,
                           (uint4*)p_wu, (uint4*)p_wg, (uint4*)p_wd,
                           (float*)p_wsu, (float*)p_wsg, (float*)p_wsd);

    dim3 g1(2 * (I_DIM / BN), T_TOK / BM);   // 48 x 32
    k_gemm_sc<<<g1, 256, GEMM_SMEM>>>(
        (const __nv_bfloat16*)p_xh, (const __nv_bfloat16*)p_xl,
        (const __nv_bfloat16*)p_wu, (const float*)p_wsu, (float*)p_up, 1,
        (const __nv_bfloat16*)p_wg, (const float*)p_wsg, (float*)p_gate, 2,
        I_DIM / BN, I_DIM, H_DIM, 0);

    // fused act+mul+split (analytic s4_b published to slot 4; no mid buffer)
    k_actmul_split<<<GS, 256>>>((uint4*)p_mh, (uint4*)p_ml, nti8);

    dim3 g3(H_DIM / BN, T_TOK / BM);   // 8 x 32
    k_gemm_sc<<<g3, 256, GEMM_SMEM>>>(
        (const __nv_bfloat16*)p_mh, (const __nv_bfloat16*)p_ml,
        (const __nv_bfloat16*)p_wd, (const float*)p_wsd, out, -1,
        (const __nv_bfloat16*)p_wd, (const float*)p_wsd, out, -1,
        H_DIM / BN, H_DIM, I_DIM, 4);
}

// round 16
// speedup vs baseline: 1.3176x; 1.2996x over previous
#include <cuda_runtime.h>
#include <cuda_bf16.h>
#include <math.h>
#include <stdint.h>

#define T_TOK 4096
#define H_DIM 2048
#define I_DIM 6144

#define RMAGIC 12582912.f   // 1.5*2^23: fma(v,inv,RMAGIC)-RMAGIC = RNE(v*inv) for |q|<2^22

// ================= device scratch (static — no runtime alloc) =================
__device__ __align__(128) __nv_bfloat16 g_xh[(size_t)T_TOK * H_DIM];
__device__ __align__(128) __nv_bfloat16 g_xl[(size_t)T_TOK * H_DIM];
__device__ __align__(128) __nv_bfloat16 g_wu[(size_t)I_DIM * H_DIM];
__device__ __align__(128) __nv_bfloat16 g_wg[(size_t)I_DIM * H_DIM];
__device__ __align__(128) __nv_bfloat16 g_wd[(size_t)H_DIM * I_DIM];
__device__ __align__(128) float g_wsu[(size_t)(H_DIM / 32) * I_DIM];
__device__ __align__(128) float g_wsg[(size_t)(H_DIM / 32) * I_DIM];
__device__ __align__(128) float g_wsd[(size_t)(I_DIM / 32) * H_DIM];
__device__ __align__(128) __nv_bfloat16 g_mh[(size_t)T_TOK * I_DIM];
__device__ __align__(128) __nv_bfloat16 g_ml[(size_t)T_TOK * I_DIM];
__device__ __align__(128) float g_up[(size_t)T_TOK * I_DIM];
__device__ __align__(128) float g_gate[(size_t)T_TOK * I_DIM];
__device__ unsigned g_absmax[8]; // 0=x 1=|up| 2=|gate| 4=s4_b*32767 5=max+(up)

#define SILU_TROUGH 0.27846455f

// ================= PTX helpers =================
__device__ __forceinline__ uint32_t smem_u32(const void* p) {
    uint32_t a;
    asm("{ .reg .u64 t; cvta.to.shared.u64 t, %1; cvt.u32.u64 %0, t; }" : "=r"(a) : "l"(p));
    return a;
}
__device__ __forceinline__ void cp16(uint32_t dst, const void* src) {
    asm volatile("cp.async.cg.shared.global [%0], [%1], 16;" :: "r"(dst), "l"(src));
}
#define CP_COMMIT() asm volatile("cp.async.commit_group;" ::: "memory")

#define LDSM4(r, addr) \
    asm volatile("ldmatrix.sync.aligned.m8n8.x4.shared.b16 {%0,%1,%2,%3}, [%4];" \
        : "=r"((r)[0]), "=r"((r)[1]), "=r"((r)[2]), "=r"((r)[3]) : "r"(addr))

#define MMA_BF16_ZC(d, a, b0, b1) \
    asm volatile("mma.sync.aligned.m16n8k16.row.col.f32.bf16.bf16.f32 " \
        "{%0,%1,%2,%3},{%4,%5,%6,%7},{%8,%9},{%10,%10,%10,%10};" \
        : "=f"((d)[0]), "=f"((d)[1]), "=f"((d)[2]), "=f"((d)[3]) \
        : "r"((a)[0]), "r"((a)[1]), "r"((a)[2]), "r"((a)[3]), \
          "r"(b0), "r"(b1), "f"(0.f))

#define MMA_BF16_ACC(d, a, b0, b1) \
    asm volatile("mma.sync.aligned.m16n8k16.row.col.f32.bf16.bf16.f32 " \
        "{%0,%1,%2,%3},{%4,%5,%6,%7},{%8,%9},{%0,%1,%2,%3};" \
        : "+f"((d)[0]), "+f"((d)[1]), "+f"((d)[2]), "+f"((d)[3]) \
        : "r"((a)[0]), "r"((a)[1]), "r"((a)[2]), "r"((a)[3]), "r"(b0), "r"(b1))

__device__ __forceinline__ float get_scale(int slot, float qmax) {
    return fmaxf(__uint_as_float(g_absmax[slot]) / qmax, 1e-12f);
}
__device__ __forceinline__ void warp_atomic_absmax(int slot, float v) {
    #pragma unroll
    for (int o = 16; o; o >>= 1) v = fmaxf(v, __shfl_xor_sync(0xffffffffu, v, o));
    if ((threadIdx.x & 31) == 0) atomicMax(&g_absmax[slot], __float_as_uint(v));
}
__device__ __forceinline__ uint32_t cvt_bf2(float lo, float hi) {
    uint32_t r;
    asm("cvt.rn.bf16x2.f32 %0, %1, %2;" : "=r"(r) : "f"(hi), "f"(lo));
    return r;
}
__device__ __forceinline__ float tanh_fast(float x) {
    float t;
    asm("tanh.approx.f32 %0, %1;" : "=f"(t) : "f"(x));
    return t;
}
__device__ __forceinline__ float silu_fast(float x) {
    float t = tanh_fast(0.5f * x);
    return x * fmaf(0.5f, t, 0.5f);
}
__device__ __forceinline__ float rne_scaled(float v, float inv) {
    return fmaf(v, inv, RMAGIC) - RMAGIC;
}

// ================= elementwise kernels =================
__global__ void k_zero() { if (threadIdx.x < 8) g_absmax[threadIdx.x] = 0u; }

__global__ void k_absmax4(const float4* __restrict__ x, size_t n4, int slot) {
    size_t i = (size_t)blockIdx.x * blockDim.x + threadIdx.x;
    size_t st = (size_t)gridDim.x * blockDim.x;
    float m = 0.f;
    for (; i < n4; i += st) {
        float4 v = x[i];
        m = fmaxf(m, fmaxf(fmaxf(fabsf(v.x), fabsf(v.y)), fmaxf(fabsf(v.z), fabsf(v.w))));
    }
    warp_atomic_absmax(slot, m);
}

__global__ void k_split_bf16(const float4* __restrict__ in, uint4* __restrict__ oh,
                             uint4* __restrict__ ol, size_t n8, int slot) {
    float s = get_scale(slot, 32767.f);
    float inv = 1.f / s;
    size_t i = (size_t)blockIdx.x * blockDim.x + threadIdx.x;
    size_t st = (size_t)gridDim.x * blockDim.x;
    for (; i < n8; i += st) {
        float4 v0 = in[2 * i], v1 = in[2 * i + 1];
        float f[8] = {v0.x, v0.y, v0.z, v0.w, v1.x, v1.y, v1.z, v1.w};
        float fh[8], fl[8];
        #pragma unroll
        for (int e = 0; e < 8; e++) {
            float q = rne_scaled(f[e], inv);
            float qh = rne_scaled(q, 0.00390625f) * 256.f;
            fh[e] = qh;
            fl[e] = q - qh;
        }
        oh[i] = make_uint4(cvt_bf2(fh[0], fh[1]), cvt_bf2(fh[2], fh[3]),
                           cvt_bf2(fh[4], fh[5]), cvt_bf2(fh[6], fh[7]));
        ol[i] = make_uint4(cvt_bf2(fl[0], fl[1]), cvt_bf2(fl[2], fl[3]),
                           cvt_bf2(fl[4], fl[5]), cvt_bf2(fl[6], fl[7]));
    }
}

__global__ void k_dqw_all(const float* __restrict__ wu, const float* __restrict__ wg,
                          const float* __restrict__ wd,
                          uint4* __restrict__ ou, uint4* __restrict__ og,
                          uint4* __restrict__ od,
                          float* __restrict__ su, float* __restrict__ sg,
                          float* __restrict__ sd) {
    const size_t NB = (size_t)I_DIM * H_DIM / 32;
    size_t i = (size_t)blockIdx.x * blockDim.x + threadIdx.x;
    size_t st = (size_t)gridDim.x * blockDim.x;
    for (; i < 3 * NB; i += st) {
        int seg = (int)(i / NB);
        size_t r = i - (size_t)seg * NB;
        const float* w; uint4* oq; float* ws; int N, K;
        if (seg == 0)      { w = wu; oq = ou; ws = su; N = I_DIM; K = H_DIM; }
        else if (seg == 1) { w = wg; oq = og; ws = sg; N = I_DIM; K = H_DIM; }
        else               { w = wd; oq = od; ws = sd; N = H_DIM; K = I_DIM; }
        int kb = K / 32;
        int n = (int)(r / kb);
        int b = (int)(r % kb);
        const float4* p = (const float4*)(w + (size_t)n * K + b * 32);
        float4 v[8];
        float m = 0.f;
        #pragma unroll
        for (int j = 0; j < 8; j++) {
            v[j] = p[j];
            m = fmaxf(m, fmaxf(fmaxf(fabsf(v[j].x), fabsf(v[j].y)),
                               fmaxf(fabsf(v[j].z), fabsf(v[j].w))));
        }
        float s = fmaxf(m / 7.0f, 1e-12f);
        float inv = 1.f / s;
        uint32_t cw[16];
        #pragma unroll
        for (int j = 0; j < 8; j++) {
            float q0 = rne_scaled(v[j].x, inv), q1 = rne_scaled(v[j].y, inv);
            float q2 = rne_scaled(v[j].z, inv), q3 = rne_scaled(v[j].w, inv);
            cw[2 * j]     = cvt_bf2(q0, q1);
            cw[2 * j + 1] = cvt_bf2(q2, q3);
        }
        uint4* dst = oq + ((size_t)n * K + b * 32) / 8;
        #pragma unroll
        for (int j = 0; j < 4; j++)
            dst[j] = make_uint4(cw[4 * j], cw[4 * j + 1], cw[4 * j + 2], cw[4 * j + 3]);
        ws[(size_t)b * N + n] = s;
    }
}

// fused act+mul+split with analytic s4_b = s2*s3*32767
__global__ void k_actmul_split(uint4* __restrict__ oh, uint4* __restrict__ ol, size_t n8) {
    float s1 = get_scale(1, 32767.f);
    float inv1 = 1.f / s1;
    float s2 = get_scale(2, 32767.f);
    float inv2 = 1.f / s2;
    float maxpos = __uint_as_float(g_absmax[5]);
    float uqm = rne_scaled(maxpos, inv1) * s1;
    float amax_act = fmaxf(silu_fast(uqm), SILU_TROUGH);
    float s3 = fmaxf(amax_act / 32767.f, 1e-12f);
    float inv3 = 1.f / s3;
    if (blockIdx.x == 0 && threadIdx.x == 0)
        g_absmax[4] = __float_as_uint(s2 * s3 * 1073676289.f);

    const float4* up = (const float4*)g_up;
    const float4* gt = (const float4*)g_gate;
    const float inv327 = 1.f / 32767.f;
    size_t i = (size_t)blockIdx.x * blockDim.x + threadIdx.x;
    size_t st = (size_t)gridDim.x * blockDim.x;
    for (; i < n8; i += st) {
        float4 u0 = up[2 * i], u1 = up[2 * i + 1];
        float4 g0 = gt[2 * i], g1 = gt[2 * i + 1];
        float fu[8] = {u0.x, u0.y, u0.z, u0.w, u1.x, u1.y, u1.z, u1.w};
        float fg[8] = {g0.x, g0.y, g0.z, g0.w, g1.x, g1.y, g1.z, g1.w};
        float fh[8], fl[8];
        #pragma unroll
        for (int e = 0; e < 8; e++) {
            float uq = rne_scaled(fu[e], inv1) * s1;
            float a = silu_fast(uq);
            float ca = rne_scaled(a, inv3);
            float cg = rne_scaled(fg[e], inv2);
            float q = rne_scaled(ca * cg, inv327);
            float qh = rne_scaled(q, 0.00390625f) * 256.f;
            fh[e] = qh;
            fl[e] = q - qh;
        }
        oh[i] = make_uint4(cvt_bf2(fh[0], fh[1]), cvt_bf2(fh[2], fh[3]),
                           cvt_bf2(fh[4], fh[5]), cvt_bf2(fh[6], fh[7]));
        ol[i] = make_uint4(cvt_bf2(fl[0], fl[1]), cvt_bf2(fl[2], fl[3]),
                           cvt_bf2(fl[4], fl[5]), cvt_bf2(fl[6], fl[7]));
    }
}

// ================= 2-term scaled-code bf16 GEMM (exact), templated tile =================
// Tile: BM = MI*32 rows x 128 cols, BK=64, 3-stage cp.async, 8 warps (2x4),
// warp tile (MI*16) x 32. Dual-launch via halfX as before.
#define BK 64
#define BNT 128
#define STAGES 3

template <int MI>
__device__ __forceinline__ void load_stage_t(
    int c, int m0, int n0, int K, int tid, uint32_t sbase,
    const __nv_bfloat16* __restrict__ Ah, const __nv_bfloat16* __restrict__ Al,
    const __nv_bfloat16* __restrict__ Bc) {
    constexpr int BMT = MI * 32;
    constexpr uint32_t A_PL = BMT * 128;
    constexpr uint32_t STG = 2 * A_PL + BNT * 128;
    int kk = c * BK;
    uint32_t st = sbase + (uint32_t)(c % STAGES) * STG;
    #pragma unroll
    for (int it = 0; it < BMT * 8 / 256; it++) {
        int idx = tid + it * 256;
        int row = idx >> 3, ch = idx & 7;
        uint32_t so = (uint32_t)row * 128 + (uint32_t)((ch ^ (row & 7)) << 4);
        size_t go = (size_t)(m0 + row) * K + kk + ch * 8;
        cp16(st + so, Ah + go);
        cp16(st + A_PL + so, Al + go);
    }
    #pragma unroll
    for (int it = 0; it < BNT * 8 / 256; it++) {
        int idx = tid + it * 256;
        int row = idx >> 3, ch = idx & 7;
        uint32_t so = (uint32_t)row * 128 + (uint32_t)((ch ^ (row & 7)) << 4);
        cp16(st + 2 * A_PL + so, Bc + (size_t)(n0 + row) * K + kk + ch * 8);
    }
    CP_COMMIT();
}

template <int MI>
__global__ void __launch_bounds__(256, 1)
k_gemm_t(const __nv_bfloat16* __restrict__ Ah, const __nv_bfloat16* __restrict__ Al,
         const __nv_bfloat16* __restrict__ B0, const float* __restrict__ Ws0,
         float* __restrict__ C0, int so0,
         const __nv_bfloat16* __restrict__ B1, const float* __restrict__ Ws1,
         float* __restrict__ C1, int so1,
         int halfX, int N, int K, int slot_in) {
    constexpr int BMT = MI * 32;
    constexpr uint32_t A_PL = BMT * 128;
    constexpr uint32_t STG = 2 * A_PL + BNT * 128;
    extern __shared__ char smem[];
    const uint32_t sbase = smem_u32(smem);
    const int tid = threadIdx.x, wid = tid >> 5, lane = tid & 31;
    const int wm = wid >> 2, wn = wid & 3;          // 2 x 4 warp grid
    const bool second = ((int)blockIdx.x >= halfX);
    const int nblk = second ? ((int)blockIdx.x - halfX) : (int)blockIdx.x;
    const __nv_bfloat16* Bc = second ? B1 : B0;
    const float* WsT = second ? Ws1 : Ws0;
    float* C = second ? C1 : C0;
    const int slot_out = second ? so1 : so0;
    const int m0 = blockIdx.y * BMT, n0 = nblk * BNT;
    const int chunks = K / BK;

    float facc[MI][4][4];
    #pragma unroll
    for (int i = 0; i < MI; i++)
        #pragma unroll
        for (int j = 0; j < 4; j++)
            #pragma unroll
            for (int e = 0; e < 4; e++) facc[i][j][e] = 0.f;

    const int a_ro = (lane & 7) + ((lane & 8) ? 8 : 0);
    const int a_chk = (lane >> 4) & 1;
    const int b_ro = (lane & 7) + ((lane & 16) ? 8 : 0);
    const int b_chk = (lane >> 3) & 1;

    load_stage_t<MI>(0, m0, n0, K, tid, sbase, Ah, Al, Bc);
    load_stage_t<MI>(1, m0, n0, K, tid, sbase, Ah, Al, Bc);

    for (int c = 0; c < chunks; ++c) {
        if (c + 1 < chunks) asm volatile("cp.async.wait_group 1;" ::: "memory");
        else                asm volatile("cp.async.wait_group 0;" ::: "memory");
        __syncthreads();
        if (c + STAGES - 1 < chunks)
            load_stage_t<MI>(c + STAGES - 1, m0, n0, K, tid, sbase, Ah, Al, Bc);

        uint32_t st = sbase + (uint32_t)(c % STAGES) * STG;
        uint32_t sAh = st, sAl = st + A_PL, sB = st + 2 * A_PL;

        #pragma unroll
        for (int kb = 0; kb < 2; kb++) {
            const float* wsr = WsT + (size_t)(c * 2 + kb) * N + n0 + wn * 32 + (lane & 3) * 2;
            float2 sc[4];
            #pragma unroll
            for (int j = 0; j < 4; j++) sc[j] = __ldg((const float2*)(wsr + j * 8));

            #pragma unroll
            for (int ks2 = 0; ks2 < 2; ks2++) {
                int ks = kb * 2 + ks2;
                uint32_t ah[MI][4], al[MI][4], bb[8];
                #pragma unroll
                for (int i = 0; i < MI; i++) {
                    int row = wm * (BMT / 2) + i * 16 + a_ro;
                    uint32_t so = (uint32_t)(((2 * ks + a_chk) ^ (row & 7)) << 4);
                    LDSM4(ah[i], sAh + (uint32_t)row * 128 + so);
                    LDSM4(al[i], sAl + (uint32_t)row * 128 + so);
                }
                #pragma unroll
                for (int j2 = 0; j2 < 2; j2++) {
                    int row = wn * 32 + j2 * 16 + b_ro;
                    uint32_t so = (uint32_t)(((2 * ks + b_chk) ^ (row & 7)) << 4);
                    LDSM4(&bb[j2 * 4], sB + (uint32_t)row * 128 + so);
                }
                #pragma unroll
                for (int i = 0; i < MI; i++)
                    #pragma unroll
                    for (int j = 0; j < 4; j++) {
                        uint32_t b0 = bb[(j >> 1) * 4 + (j & 1) * 2];
                        uint32_t b1 = bb[(j >> 1) * 4 + (j & 1) * 2 + 1];
                        float Pb[4];
                        MMA_BF16_ZC(Pb, ah[i], b0, b1);
                        MMA_BF16_ACC(Pb, al[i], b0, b1);
                        facc[i][j][0] = fmaf(Pb[0], sc[j].x, facc[i][j][0]);
                        facc[i][j][1] = fmaf(Pb[1], sc[j].y, facc[i][j][1]);
                        facc[i][j][2] = fmaf(Pb[2], sc[j].x, facc[i][j][2]);
                        facc[i][j][3] = fmaf(Pb[3], sc[j].y, facc[i][j][3]);
                    }
            }
        }
    }

    float s = get_scale(slot_in, 32767.f);
    const int g = lane >> 2, q = lane & 3;
    float mx = 0.f, mpos = 0.f;
    #pragma unroll
    for (int i = 0; i < MI; i++) {
        #pragma unroll
        for (int j = 0; j < 4; j++) {
            int row = m0 + wm * (BMT / 2) + i * 16 + g;
            int col = n0 + wn * 32 + j * 8 + q * 2;
            float v0 = facc[i][j][0] * s, v1 = facc[i][j][1] * s;
            float v2 = facc[i][j][2] * s, v3 = facc[i][j][3] * s;
            *(float2*)&C[(size_t)row * N + col] = make_float2(v0, v1);
            *(float2*)&C[(size_t)(row + 8) * N + col] = make_float2(v2, v3);
            mx = fmaxf(mx, fmaxf(fmaxf(fabsf(v0), fabsf(v1)), fmaxf(fabsf(v2), fabsf(v3))));
            mpos = fmaxf(mpos, fmaxf(fmaxf(v0, v1), fmaxf(v2, v3)));
        }
    }
    if (slot_out >= 0) warp_atomic_absmax(slot_out, mx);
    if (slot_out == 1) warp_atomic_absmax(5, fmaxf(mpos, 0.f));
}

// ================= host =================
extern "C" void kernel_launch(void* const* d_in, const int* in_sizes, int n_in,
                              void* d_out, int out_size) {
    const float* x      = (const float*)d_in[0];
    const float* w_gate = (const float*)d_in[1];
    const float* w_up   = (const float*)d_in[2];
    const float* w_down = (const float*)d_in[3];
    float* out = (float*)d_out;

    void *p_xh, *p_xl, *p_wu, *p_wg, *p_wd, *p_wsu, *p_wsg, *p_wsd;
    void *p_mh, *p_ml, *p_up, *p_gate;
    cudaGetSymbolAddress(&p_xh, g_xh);   cudaGetSymbolAddress(&p_xl, g_xl);
    cudaGetSymbolAddress(&p_wu, g_wu);   cudaGetSymbolAddress(&p_wg, g_wg);
    cudaGetSymbolAddress(&p_wd, g_wd);
    cudaGetSymbolAddress(&p_wsu, g_wsu); cudaGetSymbolAddress(&p_wsg, g_wsg);
    cudaGetSymbolAddress(&p_wsd, g_wsd);
    cudaGetSymbolAddress(&p_mh, g_mh);   cudaGetSymbolAddress(&p_ml, g_ml);
    cudaGetSymbolAddress(&p_up, g_up);   cudaGetSymbolAddress(&p_gate, g_gate);

    const int SMEM4 = STAGES * (2 * 128 * 128 + BNT * 128);  // MI=4: 3*49152 = 147456
    const int SMEM2 = STAGES * (2 * 64 * 128 + BNT * 128);   // MI=2: 3*32768 = 98304
    static bool once = false;
    if (!once) {
        cudaFuncSetAttribute(k_gemm_t<4>, cudaFuncAttributeMaxDynamicSharedMemorySize, SMEM4);
        cudaFuncSetAttribute(k_gemm_t<2>, cudaFuncAttributeMaxDynamicSharedMemorySize, SMEM2);
        once = true;
    }

    const int GS = 1184;
    const size_t nx4 = (size_t)T_TOK * H_DIM / 4;
    const size_t nx8 = (size_t)T_TOK * H_DIM / 8;
    const size_t nti8 = (size_t)T_TOK * I_DIM / 8;

    k_zero<<<1, 32>>>();
    k_absmax4<<<GS, 256>>>((const float4*)x, nx4, 0);
    k_split_bf16<<<GS, 256>>>((const float4*)x, (uint4*)p_xh, (uint4*)p_xl, nx8, 0);
    k_dqw_all<<<GS, 256>>>(w_up, w_gate, w_down,
                           (uint4*)p_wu, (uint4*)p_wg, (uint4*)p_wd,
                           (float*)p_wsu, (float*)p_wsg, (float*)p_wsd);

    // merged up+gate GEMM, 128x128 tiles: x-blocks [0,48) -> up, [48,96) -> gate
    dim3 g1(2 * (I_DIM / BNT), T_TOK / 128);   // 96 x 32 = 3072 CTAs
    k_gemm_t<4><<<g1, 256, SMEM4>>>(
        (const __nv_bfloat16*)p_xh, (const __nv_bfloat16*)p_xl,
        (const __nv_bfloat16*)p_wu, (const float*)p_wsu, (float*)p_up, 1,
        (const __nv_bfloat16*)p_wg, (const float*)p_wsg, (float*)p_gate, 2,
        I_DIM / BNT, I_DIM, H_DIM, 0);

    k_actmul_split<<<GS, 256>>>((uint4*)p_mh, (uint4*)p_ml, nti8);

    // down GEMM, 64x128 tiles: 16 x 64 = 1024 CTAs (7 waves, 1.2% tail)
    dim3 g3(H_DIM / BNT, T_TOK / 64);
    k_gemm_t<2><<<g3, 256, SMEM2>>>(
        (const __nv_bfloat16*)p_mh, (const __nv_bfloat16*)p_ml,
        (const __nv_bfloat16*)p_wd, (const float*)p_wsd, out, -1,
        (const __nv_bfloat16*)p_wd, (const float*)p_wsd, out, -1,
        H_DIM / BNT, H_DIM, I_DIM, 4);
}

// round 17
// speedup vs baseline: 1.4501x; 1.1006x over previous
#include <cuda_runtime.h>
#include <cuda_bf16.h>
#include <math.h>
#include <stdint.h>

#define T_TOK 4096
#define H_DIM 2048
#define I_DIM 6144

#define RMAGIC 12582912.f   // 1.5*2^23: fma(v,inv,RMAGIC)-RMAGIC = RNE(v*inv) for |q|<2^22

// ================= device scratch (static — no runtime alloc) =================
__device__ __align__(128) __nv_bfloat16 g_xh[(size_t)T_TOK * H_DIM];
__device__ __align__(128) __nv_bfloat16 g_xl[(size_t)T_TOK * H_DIM];
__device__ __align__(128) __nv_bfloat16 g_wu[(size_t)I_DIM * H_DIM];
__device__ __align__(128) __nv_bfloat16 g_wg[(size_t)I_DIM * H_DIM];
__device__ __align__(128) __nv_bfloat16 g_wd[(size_t)H_DIM * I_DIM];
__device__ __align__(128) float g_wsu[(size_t)(H_DIM / 32) * I_DIM];
__device__ __align__(128) float g_wsg[(size_t)(H_DIM / 32) * I_DIM];
__device__ __align__(128) float g_wsd[(size_t)(I_DIM / 32) * H_DIM];
__device__ __align__(128) __nv_bfloat16 g_mh[(size_t)T_TOK * I_DIM];
__device__ __align__(128) __nv_bfloat16 g_ml[(size_t)T_TOK * I_DIM];
__device__ __align__(128) float g_up[(size_t)T_TOK * I_DIM];
__device__ __align__(128) float g_gate[(size_t)T_TOK * I_DIM];
__device__ unsigned g_absmax[8]; // 0=x 1=|up| 2=|gate| 4=s4_b*32767 5=max+(up)

#define SILU_TROUGH 0.27846455f

// ================= PTX helpers =================
__device__ __forceinline__ uint32_t smem_u32(const void* p) {
    uint32_t a;
    asm("{ .reg .u64 t; cvta.to.shared.u64 t, %1; cvt.u32.u64 %0, t; }" : "=r"(a) : "l"(p));
    return a;
}
__device__ __forceinline__ void cp16(uint32_t dst, const void* src) {
    asm volatile("cp.async.cg.shared.global [%0], [%1], 16;" :: "r"(dst), "l"(src));
}
#define CP_COMMIT() asm volatile("cp.async.commit_group;" ::: "memory")

#define LDSM4(r, addr) \
    asm volatile("ldmatrix.sync.aligned.m8n8.x4.shared.b16 {%0,%1,%2,%3}, [%4];" \
        : "=r"((r)[0]), "=r"((r)[1]), "=r"((r)[2]), "=r"((r)[3]) : "r"(addr))

#define MMA_BF16_ZC(d, a, b0, b1) \
    asm volatile("mma.sync.aligned.m16n8k16.row.col.f32.bf16.bf16.f32 " \
        "{%0,%1,%2,%3},{%4,%5,%6,%7},{%8,%9},{%10,%10,%10,%10};" \
        : "=f"((d)[0]), "=f"((d)[1]), "=f"((d)[2]), "=f"((d)[3]) \
        : "r"((a)[0]), "r"((a)[1]), "r"((a)[2]), "r"((a)[3]), \
          "r"(b0), "r"(b1), "f"(0.f))

#define MMA_BF16_ACC(d, a, b0, b1) \
    asm volatile("mma.sync.aligned.m16n8k16.row.col.f32.bf16.bf16.f32 " \
        "{%0,%1,%2,%3},{%4,%5,%6,%7},{%8,%9},{%0,%1,%2,%3};" \
        : "+f"((d)[0]), "+f"((d)[1]), "+f"((d)[2]), "+f"((d)[3]) \
        : "r"((a)[0]), "r"((a)[1]), "r"((a)[2]), "r"((a)[3]), "r"(b0), "r"(b1))

__device__ __forceinline__ float get_scale(int slot, float qmax) {
    return fmaxf(__uint_as_float(g_absmax[slot]) / qmax, 1e-12f);
}
__device__ __forceinline__ void warp_atomic_absmax(int slot, float v) {
    #pragma unroll
    for (int o = 16; o; o >>= 1) v = fmaxf(v, __shfl_xor_sync(0xffffffffu, v, o));
    if ((threadIdx.x & 31) == 0) atomicMax(&g_absmax[slot], __float_as_uint(v));
}
__device__ __forceinline__ uint32_t cvt_bf2(float lo, float hi) {
    uint32_t r;
    asm("cvt.rn.bf16x2.f32 %0, %1, %2;" : "=r"(r) : "f"(hi), "f"(lo));
    return r;
}
__device__ __forceinline__ float tanh_fast(float x) {
    float t;
    asm("tanh.approx.f32 %0, %1;" : "=f"(t) : "f"(x));
    return t;
}
__device__ __forceinline__ float silu_fast(float x) {
    float t = tanh_fast(0.5f * x);
    return x * fmaf(0.5f, t, 0.5f);
}
__device__ __forceinline__ float rne_scaled(float v, float inv) {
    return fmaf(v, inv, RMAGIC) - RMAGIC;
}

// ================= elementwise kernels =================
__global__ void k_zero() { if (threadIdx.x < 8) g_absmax[threadIdx.x] = 0u; }

__global__ void k_absmax4(const float4* __restrict__ x, size_t n4, int slot) {
    size_t i = (size_t)blockIdx.x * blockDim.x + threadIdx.x;
    size_t st = (size_t)gridDim.x * blockDim.x;
    float m = 0.f;
    for (; i < n4; i += st) {
        float4 v = x[i];
        m = fmaxf(m, fmaxf(fmaxf(fabsf(v.x), fabsf(v.y)), fmaxf(fabsf(v.z), fabsf(v.w))));
    }
    warp_atomic_absmax(slot, m);
}

__global__ void k_split_bf16(const float4* __restrict__ in, uint4* __restrict__ oh,
                             uint4* __restrict__ ol, size_t n8, int slot) {
    float s = get_scale(slot, 32767.f);
    float inv = 1.f / s;
    size_t i = (size_t)blockIdx.x * blockDim.x + threadIdx.x;
    size_t st = (size_t)gridDim.x * blockDim.x;
    for (; i < n8; i += st) {
        float4 v0 = in[2 * i], v1 = in[2 * i + 1];
        float f[8] = {v0.x, v0.y, v0.z, v0.w, v1.x, v1.y, v1.z, v1.w};
        float fh[8], fl[8];
        #pragma unroll
        for (int e = 0; e < 8; e++) {
            float q = rne_scaled(f[e], inv);
            float qh = rne_scaled(q, 0.00390625f) * 256.f;
            fh[e] = qh;
            fl[e] = q - qh;
        }
        oh[i] = make_uint4(cvt_bf2(fh[0], fh[1]), cvt_bf2(fh[2], fh[3]),
                           cvt_bf2(fh[4], fh[5]), cvt_bf2(fh[6], fh[7]));
        ol[i] = make_uint4(cvt_bf2(fl[0], fl[1]), cvt_bf2(fl[2], fl[3]),
                           cvt_bf2(fl[4], fl[5]), cvt_bf2(fl[6], fl[7]));
    }
}

__global__ void k_dqw_all(const float* __restrict__ wu, const float* __restrict__ wg,
                          const float* __restrict__ wd,
                          uint4* __restrict__ ou, uint4* __restrict__ og,
                          uint4* __restrict__ od,
                          float* __restrict__ su, float* __restrict__ sg,
                          float* __restrict__ sd) {
    const size_t NB = (size_t)I_DIM * H_DIM / 32;
    size_t i = (size_t)blockIdx.x * blockDim.x + threadIdx.x;
    size_t st = (size_t)gridDim.x * blockDim.x;
    for (; i < 3 * NB; i += st) {
        int seg = (int)(i / NB);
        size_t r = i - (size_t)seg * NB;
        const float* w; uint4* oq; float* ws; int N, K;
        if (seg == 0)      { w = wu; oq = ou; ws = su; N = I_DIM; K = H_DIM; }
        else if (seg == 1) { w = wg; oq = og; ws = sg; N = I_DIM; K = H_DIM; }
        else               { w = wd; oq = od; ws = sd; N = H_DIM; K = I_DIM; }
        int kb = K / 32;
        int n = (int)(r / kb);
        int b = (int)(r % kb);
        const float4* p = (const float4*)(w + (size_t)n * K + b * 32);
        float4 v[8];
        float m = 0.f;
        #pragma unroll
        for (int j = 0; j < 8; j++) {
            v[j] = p[j];
            m = fmaxf(m, fmaxf(fmaxf(fabsf(v[j].x), fabsf(v[j].y)),
                               fmaxf(fabsf(v[j].z), fabsf(v[j].w))));
        }
        float s = fmaxf(m / 7.0f, 1e-12f);
        float inv = 1.f / s;
        uint32_t cw[16];
        #pragma unroll
        for (int j = 0; j < 8; j++) {
            float q0 = rne_scaled(v[j].x, inv), q1 = rne_scaled(v[j].y, inv);
            float q2 = rne_scaled(v[j].z, inv), q3 = rne_scaled(v[j].w, inv);
            cw[2 * j]     = cvt_bf2(q0, q1);
            cw[2 * j + 1] = cvt_bf2(q2, q3);
        }
        uint4* dst = oq + ((size_t)n * K + b * 32) / 8;
        #pragma unroll
        for (int j = 0; j < 4; j++)
            dst[j] = make_uint4(cw[4 * j], cw[4 * j + 1], cw[4 * j + 2], cw[4 * j + 3]);
        ws[(size_t)b * N + n] = s;
    }
}

// fused act+mul+split with analytic s4_b = s2*s3*32767
__global__ void k_actmul_split(uint4* __restrict__ oh, uint4* __restrict__ ol, size_t n8) {
    float s1 = get_scale(1, 32767.f);
    float inv1 = 1.f / s1;
    float s2 = get_scale(2, 32767.f);
    float inv2 = 1.f / s2;
    float maxpos = __uint_as_float(g_absmax[5]);
    float uqm = rne_scaled(maxpos, inv1) * s1;
    float amax_act = fmaxf(silu_fast(uqm), SILU_TROUGH);
    float s3 = fmaxf(amax_act / 32767.f, 1e-12f);
    float inv3 = 1.f / s3;
    if (blockIdx.x == 0 && threadIdx.x == 0)
        g_absmax[4] = __float_as_uint(s2 * s3 * 1073676289.f);

    const float4* up = (const float4*)g_up;
    const float4* gt = (const float4*)g_gate;
    const float inv327 = 1.f / 32767.f;
    size_t i = (size_t)blockIdx.x * blockDim.x + threadIdx.x;
    size_t st = (size_t)gridDim.x * blockDim.x;
    for (; i < n8; i += st) {
        float4 u0 = up[2 * i], u1 = up[2 * i + 1];
        float4 g0 = gt[2 * i], g1 = gt[2 * i + 1];
        float fu[8] = {u0.x, u0.y, u0.z, u0.w, u1.x, u1.y, u1.z, u1.w};
        float fg[8] = {g0.x, g0.y, g0.z, g0.w, g1.x, g1.y, g1.z, g1.w};
        float fh[8], fl[8];
        #pragma unroll
        for (int e = 0; e < 8; e++) {
            float uq = rne_scaled(fu[e], inv1) * s1;
            float a = silu_fast(uq);
            float ca = rne_scaled(a, inv3);
            float cg = rne_scaled(fg[e], inv2);
            float q = rne_scaled(ca * cg, inv327);
            float qh = rne_scaled(q, 0.00390625f) * 256.f;
            fh[e] = qh;
            fl[e] = q - qh;
        }
        oh[i] = make_uint4(cvt_bf2(fh[0], fh[1]), cvt_bf2(fh[2], fh[3]),
                           cvt_bf2(fh[4], fh[5]), cvt_bf2(fh[6], fh[7]));
        ol[i] = make_uint4(cvt_bf2(fl[0], fl[1]), cvt_bf2(fl[2], fl[3]),
                           cvt_bf2(fl[4], fl[5]), cvt_bf2(fl[6], fl[7]));
    }
}

// ================= 2-term scaled-code bf16 GEMM (exact), templated tile =================
// Tile: BM = MI*32 rows x 128 cols, BK=64, 3-stage cp.async, 8 warps (2x4),
// warp tile (MI*16) x 32. 2 CTAs/SM to cover sync bubbles. Dual-launch via halfX.
#define BK 64
#define BNT 128
#define STAGES 3

template <int MI>
__device__ __forceinline__ void load_stage_t(
    int c, int m0, int n0, int K, int tid, uint32_t sbase,
    const __nv_bfloat16* __restrict__ Ah, const __nv_bfloat16* __restrict__ Al,
    const __nv_bfloat16* __restrict__ Bc) {
    constexpr int BMT = MI * 32;
    constexpr uint32_t A_PL = BMT * 128;
    constexpr uint32_t STG = 2 * A_PL + BNT * 128;
    int kk = c * BK;
    uint32_t st = sbase + (uint32_t)(c % STAGES) * STG;
    #pragma unroll
    for (int it = 0; it < BMT * 8 / 256; it++) {
        int idx = tid + it * 256;
        int row = idx >> 3, ch = idx & 7;
        uint32_t so = (uint32_t)row * 128 + (uint32_t)((ch ^ (row & 7)) << 4);
        size_t go = (size_t)(m0 + row) * K + kk + ch * 8;
        cp16(st + so, Ah + go);
        cp16(st + A_PL + so, Al + go);
    }
    #pragma unroll
    for (int it = 0; it < BNT * 8 / 256; it++) {
        int idx = tid + it * 256;
        int row = idx >> 3, ch = idx & 7;
        uint32_t so = (uint32_t)row * 128 + (uint32_t)((ch ^ (row & 7)) << 4);
        cp16(st + 2 * A_PL + so, Bc + (size_t)(n0 + row) * K + kk + ch * 8);
    }
    CP_COMMIT();
}

template <int MI>
__global__ void __launch_bounds__(256, 2)
k_gemm_t(const __nv_bfloat16* __restrict__ Ah, const __nv_bfloat16* __restrict__ Al,
         const __nv_bfloat16* __restrict__ B0, const float* __restrict__ Ws0,
         float* __restrict__ C0, int so0,
         const __nv_bfloat16* __restrict__ B1, const float* __restrict__ Ws1,
         float* __restrict__ C1, int so1,
         int halfX, int N, int K, int slot_in) {
    constexpr int BMT = MI * 32;
    constexpr uint32_t A_PL = BMT * 128;
    constexpr uint32_t STG = 2 * A_PL + BNT * 128;
    extern __shared__ char smem[];
    const uint32_t sbase = smem_u32(smem);
    const int tid = threadIdx.x, wid = tid >> 5, lane = tid & 31;
    const int wm = wid >> 2, wn = wid & 3;          // 2 x 4 warp grid
    const bool second = ((int)blockIdx.x >= halfX);
    const int nblk = second ? ((int)blockIdx.x - halfX) : (int)blockIdx.x;
    const __nv_bfloat16* Bc = second ? B1 : B0;
    const float* WsT = second ? Ws1 : Ws0;
    float* C = second ? C1 : C0;
    const int slot_out = second ? so1 : so0;
    const int m0 = blockIdx.y * BMT, n0 = nblk * BNT;
    const int chunks = K / BK;

    float facc[MI][4][4];
    #pragma unroll
    for (int i = 0; i < MI; i++)
        #pragma unroll
        for (int j = 0; j < 4; j++)
            #pragma unroll
            for (int e = 0; e < 4; e++) facc[i][j][e] = 0.f;

    const int a_ro = (lane & 7) + ((lane & 8) ? 8 : 0);
    const int a_chk = (lane >> 4) & 1;
    const int b_ro = (lane & 7) + ((lane & 16) ? 8 : 0);
    const int b_chk = (lane >> 3) & 1;

    load_stage_t<MI>(0, m0, n0, K, tid, sbase, Ah, Al, Bc);
    load_stage_t<MI>(1, m0, n0, K, tid, sbase, Ah, Al, Bc);

    for (int c = 0; c < chunks; ++c) {
        if (c + 1 < chunks) asm volatile("cp.async.wait_group 1;" ::: "memory");
        else                asm volatile("cp.async.wait_group 0;" ::: "memory");
        __syncthreads();
        if (c + STAGES - 1 < chunks)
            load_stage_t<MI>(c + STAGES - 1, m0, n0, K, tid, sbase, Ah, Al, Bc);

        uint32_t st = sbase + (uint32_t)(c % STAGES) * STG;
        uint32_t sAh = st, sAl = st + A_PL, sB = st + 2 * A_PL;

        #pragma unroll
        for (int kb = 0; kb < 2; kb++) {
            const float* wsr = WsT + (size_t)(c * 2 + kb) * N + n0 + wn * 32 + (lane & 3) * 2;
            float2 sc[4];
            #pragma unroll
            for (int j = 0; j < 4; j++) sc[j] = __ldg((const float2*)(wsr + j * 8));

            #pragma unroll
            for (int ks2 = 0; ks2 < 2; ks2++) {
                int ks = kb * 2 + ks2;
                uint32_t ah[MI][4], al[MI][4], bb[8];
                #pragma unroll
                for (int i = 0; i < MI; i++) {
                    int row = wm * (BMT / 2) + i * 16 + a_ro;
                    uint32_t so = (uint32_t)(((2 * ks + a_chk) ^ (row & 7)) << 4);
                    LDSM4(ah[i], sAh + (uint32_t)row * 128 + so);
                    LDSM4(al[i], sAl + (uint32_t)row * 128 + so);
                }
                #pragma unroll
                for (int j2 = 0; j2 < 2; j2++) {
                    int row = wn * 32 + j2 * 16 + b_ro;
                    uint32_t so = (uint32_t)(((2 * ks + b_chk) ^ (row & 7)) << 4);
                    LDSM4(&bb[j2 * 4], sB + (uint32_t)row * 128 + so);
                }
                #pragma unroll
                for (int i = 0; i < MI; i++)
                    #pragma unroll
                    for (int j = 0; j < 4; j++) {
                        uint32_t b0 = bb[(j >> 1) * 4 + (j & 1) * 2];
                        uint32_t b1 = bb[(j >> 1) * 4 + (j & 1) * 2 + 1];
                        float Pb[4];
                        MMA_BF16_ZC(Pb, ah[i], b0, b1);
                        MMA_BF16_ACC(Pb, al[i], b0, b1);
                        facc[i][j][0] = fmaf(Pb[0], sc[j].x, facc[i][j][0]);
                        facc[i][j][1] = fmaf(Pb[1], sc[j].y, facc[i][j][1]);
                        facc[i][j][2] = fmaf(Pb[2], sc[j].x, facc[i][j][2]);
                        facc[i][j][3] = fmaf(Pb[3], sc[j].y, facc[i][j][3]);
                    }
            }
        }
    }

    float s = get_scale(slot_in, 32767.f);
    const int g = lane >> 2, q = lane & 3;
    float mx = 0.f, mpos = 0.f;
    #pragma unroll
    for (int i = 0; i < MI; i++) {
        #pragma unroll
        for (int j = 0; j < 4; j++) {
            int row = m0 + wm * (BMT / 2) + i * 16 + g;
            int col = n0 + wn * 32 + j * 8 + q * 2;
            float v0 = facc[i][j][0] * s, v1 = facc[i][j][1] * s;
            float v2 = facc[i][j][2] * s, v3 = facc[i][j][3] * s;
            *(float2*)&C[(size_t)row * N + col] = make_float2(v0, v1);
            *(float2*)&C[(size_t)(row + 8) * N + col] = make_float2(v2, v3);
            mx = fmaxf(mx, fmaxf(fmaxf(fabsf(v0), fabsf(v1)), fmaxf(fabsf(v2), fabsf(v3))));
            mpos = fmaxf(mpos, fmaxf(fmaxf(v0, v1), fmaxf(v2, v3)));
        }
    }
    if (slot_out >= 0) warp_atomic_absmax(slot_out, mx);
    if (slot_out == 1) warp_atomic_absmax(5, fmaxf(mpos, 0.f));
}

// ================= host =================
extern "C" void kernel_launch(void* const* d_in, const int* in_sizes, int n_in,
                              void* d_out, int out_size) {
    const float* x      = (const float*)d_in[0];
    const float* w_gate = (const float*)d_in[1];
    const float* w_up   = (const float*)d_in[2];
    const float* w_down = (const float*)d_in[3];
    float* out = (float*)d_out;

    void *p_xh, *p_xl, *p_wu, *p_wg, *p_wd, *p_wsu, *p_wsg, *p_wsd;
    void *p_mh, *p_ml, *p_up, *p_gate;
    cudaGetSymbolAddress(&p_xh, g_xh);   cudaGetSymbolAddress(&p_xl, g_xl);
    cudaGetSymbolAddress(&p_wu, g_wu);   cudaGetSymbolAddress(&p_wg, g_wg);
    cudaGetSymbolAddress(&p_wd, g_wd);
    cudaGetSymbolAddress(&p_wsu, g_wsu); cudaGetSymbolAddress(&p_wsg, g_wsg);
    cudaGetSymbolAddress(&p_wsd, g_wsd);
    cudaGetSymbolAddress(&p_mh, g_mh);   cudaGetSymbolAddress(&p_ml, g_ml);
    cudaGetSymbolAddress(&p_up, g_up);   cudaGetSymbolAddress(&p_gate, g_gate);

    const int SMEM2 = STAGES * (2 * 64 * 128 + BNT * 128);   // MI=2: 3*32768 = 98304
    static bool once = false;
    if (!once) {
        cudaFuncSetAttribute(k_gemm_t<2>, cudaFuncAttributeMaxDynamicSharedMemorySize, SMEM2);
        once = true;
    }

    const int GS = 1184;
    const size_t nx4 = (size_t)T_TOK * H_DIM / 4;
    const size_t nx8 = (size_t)T_TOK * H_DIM / 8;
    const size_t nti8 = (size_t)T_TOK * I_DIM / 8;

    k_zero<<<1, 32>>>();
    k_absmax4<<<GS, 256>>>((const float4*)x, nx4, 0);
    k_split_bf16<<<GS, 256>>>((const float4*)x, (uint4*)p_xh, (uint4*)p_xl, nx8, 0);
    k_dqw_all<<<GS, 256>>>(w_up, w_gate, w_down,
                           (uint4*)p_wu, (uint4*)p_wg, (uint4*)p_wd,
                           (float*)p_wsu, (float*)p_wsg, (float*)p_wsd);

    // merged up+gate GEMM, 64x128 tiles, 2 CTAs/SM: [0,48) -> up, [48,96) -> gate
    dim3 g1(2 * (I_DIM / BNT), T_TOK / 64);   // 96 x 64 = 6144 CTAs
    k_gemm_t<2><<<g1, 256, SMEM2>>>(
        (const __nv_bfloat16*)p_xh, (const __nv_bfloat16*)p_xl,
        (const __nv_bfloat16*)p_wu, (const float*)p_wsu, (float*)p_up, 1,
        (const __nv_bfloat16*)p_wg, (const float*)p_wsg, (float*)p_gate, 2,
        I_DIM / BNT, I_DIM, H_DIM, 0);

    k_actmul_split<<<GS, 256>>>((uint4*)p_mh, (uint4*)p_ml, nti8);

    // down GEMM, 64x128 tiles, 2 CTAs/SM: 16 x 64 = 1024 CTAs
    dim3 g3(H_DIM / BNT, T_TOK / 64);
    k_gemm_t<2><<<g3, 256, SMEM2>>>(
        (const __nv_bfloat16*)p_mh, (const __nv_bfloat16*)p_ml,
        (const __nv_bfloat16*)p_wd, (const float*)p_wsd, out, -1,
        (const __nv_bfloat16*)p_wd, (const float*)p_wsd, out, -1,
        H_DIM / BNT, H_DIM, I_DIM, 4);
}